// round 2
// baseline (speedup 1.0000x reference)
#include <cuda_runtime.h>
#include <math.h>

#define L_SEQ   2048
#define D_MODEL 1024
#define N_HEADS 16
#define D_HEAD  64
#define BATCH   2
#define BH      (BATCH * N_HEADS)     /* 32  */
#define M_ROWS  (BATCH * L_SEQ)       /* 4096 */
#define SCALE_F 0.125f                /* Dh^-0.5 */
#define EPS_F   1e-9f
#define P_PITCH 132                   /* P smem pitch (mult of 4 for STS.128) */

/* ------------ scratch (static device globals: no allocation allowed) ------ */
__device__ __align__(16) float g_q[BH * L_SEQ * D_HEAD];
__device__ __align__(16) float g_k[BH * L_SEQ * D_HEAD];
__device__ __align__(16) float g_v[BH * L_SEQ * D_HEAD];
__device__ __align__(16) float g_x[(size_t)M_ROWS * D_MODEL];

/* ===========================================================================
 * GEMM: C = A @ B^T (+bias).  A:[4096,1024] rm, B:[1024,1024] rm.
 * head_mode=1: scatter C into per-head layout [B,H,L,Dh] (for q/k/v).
 * head_mode=0: plain row-major [4096,1024] with bias (final output).
 * 128x128 block, 8x8 thread tile, 256 threads, BK=16.
 * ========================================================================= */
__global__ __launch_bounds__(256)
void gemm_nt(const float* __restrict__ A, const float* __restrict__ B,
             float* __restrict__ C, const float* __restrict__ bias,
             int head_mode)
{
    __shared__ float As[16][128];
    __shared__ float Bs[16][128];
    const int K = D_MODEL;

    const int tid = threadIdx.x;
    const int tx = tid & 15, ty = tid >> 4;
    const int m0 = blockIdx.y * 128, n0 = blockIdx.x * 128;
    const int lrow = tid >> 2;
    const int lcol = (tid & 3) * 4;

    float acc[8][8];
#pragma unroll
    for (int i = 0; i < 8; ++i)
#pragma unroll
        for (int j = 0; j < 8; ++j) acc[i][j] = 0.f;

    for (int k0 = 0; k0 < K; k0 += 16) {
#pragma unroll
        for (int rr = 0; rr < 2; ++rr) {
            int r = lrow + rr * 64;
            float4 a = *reinterpret_cast<const float4*>(&A[(size_t)(m0 + r) * K + k0 + lcol]);
            As[lcol + 0][r] = a.x; As[lcol + 1][r] = a.y;
            As[lcol + 2][r] = a.z; As[lcol + 3][r] = a.w;
            float4 b = *reinterpret_cast<const float4*>(&B[(size_t)(n0 + r) * K + k0 + lcol]);
            Bs[lcol + 0][r] = b.x; Bs[lcol + 1][r] = b.y;
            Bs[lcol + 2][r] = b.z; Bs[lcol + 3][r] = b.w;
        }
        __syncthreads();
#pragma unroll
        for (int k = 0; k < 16; ++k) {
            float ar[8], br[8];
            *reinterpret_cast<float4*>(&ar[0]) = *reinterpret_cast<const float4*>(&As[k][ty * 8]);
            *reinterpret_cast<float4*>(&ar[4]) = *reinterpret_cast<const float4*>(&As[k][ty * 8 + 4]);
            *reinterpret_cast<float4*>(&br[0]) = *reinterpret_cast<const float4*>(&Bs[k][tx * 8]);
            *reinterpret_cast<float4*>(&br[4]) = *reinterpret_cast<const float4*>(&Bs[k][tx * 8 + 4]);
#pragma unroll
            for (int i = 0; i < 8; ++i)
#pragma unroll
                for (int j = 0; j < 8; ++j) acc[i][j] += ar[i] * br[j];
        }
        __syncthreads();
    }

    if (head_mode) {
#pragma unroll
        for (int i = 0; i < 8; ++i) {
            int m = m0 + ty * 8 + i;
            int b = m >> 11, l = m & 2047;
#pragma unroll
            for (int j = 0; j < 8; ++j) {
                int n = n0 + tx * 8 + j;
                int h = n >> 6, dh = n & 63;
                C[(((size_t)(b * N_HEADS + h) * L_SEQ + l) << 6) + dh] = acc[i][j];
            }
        }
    } else {
#pragma unroll
        for (int i = 0; i < 8; ++i) {
            int m = m0 + ty * 8 + i;
#pragma unroll
            for (int j = 0; j < 8; ++j) {
                int n = n0 + tx * 8 + j;
                C[(size_t)m * D_MODEL + n] = acc[i][j] + bias[n];
            }
        }
    }
}

/* ===========================================================================
 * Fused Euclidean flash-attention.
 * Grid: (L/128 q-tiles, B*H).  256 threads as 16x16; 8x8 S micro-tiles.
 * Q/K in smem transposed [64][128] with XOR-4 swizzle on the row index
 * (kills the 16-way transposed-store conflicts -> ~2-way).
 * Online softmax over w = 1/(dist*scale + eps); P staged via smem (pitch 132,
 * broadcast reads, vector writes); P@V register-tiled 8x4 per thread.
 * ========================================================================= */
__device__ __forceinline__ int swz(int d, int r)
{
    return d * 128 + (r ^ (((d >> 2) & 7) << 2));
}

__global__ __launch_bounds__(256)
void attn_kernel(const float* __restrict__ Qh, const float* __restrict__ Kh,
                 const float* __restrict__ Vh, float* __restrict__ Xout)
{
    extern __shared__ float sm[];
    float* Qs  = sm;                    /* [64][128] swizzled     */
    float* Ks  = Qs + 64 * 128;         /* [64][128] swizzled     */
    float* Vs  = Ks + 64 * 128;         /* [128][64] row-major    */
    float* Ps  = Vs + 128 * 64;         /* [128][P_PITCH]         */
    float* q2s = Ps + 128 * P_PITCH;    /* [128]                  */
    float* k2s = q2s + 128;             /* [128]                  */

    const int tid = threadIdx.x;
    const int tx = tid & 15, ty = tid >> 4;
    const int bh = blockIdx.y;
    const int q0 = blockIdx.x * 128;

    const float* Qb  = Qh + ((size_t)bh * L_SEQ + q0) * D_HEAD;
    const float* Kb0 = Kh + (size_t)bh * L_SEQ * D_HEAD;
    const float* Vb0 = Vh + (size_t)bh * L_SEQ * D_HEAD;

    /* load Q tile transposed+swizzled: 2048 float4s, 8 per thread */
#pragma unroll
    for (int it = 0; it < 8; ++it) {
        int idx = tid + it * 256;
        int r = idx >> 4;
        int c = (idx & 15) * 4;
        float4 q4 = reinterpret_cast<const float4*>(Qb)[idx];
        Qs[swz(c + 0, r)] = q4.x;
        Qs[swz(c + 1, r)] = q4.y;
        Qs[swz(c + 2, r)] = q4.z;
        Qs[swz(c + 3, r)] = q4.w;
    }
    __syncthreads();
    if (tid < 128) {
        float s = 0.f;
#pragma unroll
        for (int d = 0; d < 64; ++d) { float x = Qs[swz(d, tid)]; s += x * x; }
        q2s[tid] = s;
    }

    float Mrow[8], Lrow[8], Oacc[8][4];
#pragma unroll
    for (int i = 0; i < 8; ++i) {
        Mrow[i] = -1e30f; Lrow[i] = 0.f;
#pragma unroll
        for (int j = 0; j < 4; ++j) Oacc[i][j] = 0.f;
    }
    __syncthreads();

    for (int kt = 0; kt < L_SEQ / 128; ++kt) {
        const float* Kb = Kb0 + (size_t)kt * 128 * D_HEAD;
        const float* Vb = Vb0 + (size_t)kt * 128 * D_HEAD;
#pragma unroll
        for (int it = 0; it < 8; ++it) {
            int idx = tid + it * 256;
            int r = idx >> 4;
            int c = (idx & 15) * 4;
            float4 k4 = reinterpret_cast<const float4*>(Kb)[idx];
            Ks[swz(c + 0, r)] = k4.x;
            Ks[swz(c + 1, r)] = k4.y;
            Ks[swz(c + 2, r)] = k4.z;
            Ks[swz(c + 3, r)] = k4.w;
            reinterpret_cast<float4*>(Vs)[idx] = reinterpret_cast<const float4*>(Vb)[idx];
        }
        __syncthreads();
        if (tid < 128) {
            float s = 0.f;
#pragma unroll
            for (int d = 0; d < 64; ++d) { float x = Ks[swz(d, tid)]; s += x * x; }
            k2s[tid] = s;
        }
        __syncthreads();

        /* ---- S = q.k (register tiled over Dh=64) ---- */
        float acc[8][8];
#pragma unroll
        for (int i = 0; i < 8; ++i)
#pragma unroll
            for (int j = 0; j < 8; ++j) acc[i][j] = 0.f;

#pragma unroll
        for (int d = 0; d < 64; ++d) {
            const int s  = (d >> 2) & 7;
            const int xh = (s >> 1) << 3;   /* xor into the *8 group bits */
            const int o0 = (s & 1) << 2;    /* 0 or 4                     */
            float aq[8], ak[8];
            {
                int b_ = d * 128 + ((ty << 3) ^ xh);
                *reinterpret_cast<float4*>(&aq[0]) = *reinterpret_cast<const float4*>(&Qs[b_ + o0]);
                *reinterpret_cast<float4*>(&aq[4]) = *reinterpret_cast<const float4*>(&Qs[b_ + (4 - o0)]);
            }
            {
                int b_ = d * 128 + ((tx << 3) ^ xh);
                *reinterpret_cast<float4*>(&ak[0]) = *reinterpret_cast<const float4*>(&Ks[b_ + o0]);
                *reinterpret_cast<float4*>(&ak[4]) = *reinterpret_cast<const float4*>(&Ks[b_ + (4 - o0)]);
            }
#pragma unroll
            for (int i = 0; i < 8; ++i)
#pragma unroll
                for (int j = 0; j < 8; ++j) acc[i][j] += aq[i] * ak[j];
        }

        /* ---- euclid weights + online softmax ---- */
#pragma unroll
        for (int i = 0; i < 8; ++i) {
            float q2 = q2s[ty * 8 + i];
            float w[8];
            float mloc = -1e30f;
#pragma unroll
            for (int j = 0; j < 8; ++j) {
                float d2   = q2 + k2s[tx * 8 + j] - 2.f * acc[i][j];
                float dist = sqrtf(fmaxf(d2, 0.f));
                float wv   = __fdividef(1.f, dist * SCALE_F + EPS_F);
                w[j] = wv;
                mloc = fmaxf(mloc, wv);
            }
#pragma unroll
            for (int off = 8; off > 0; off >>= 1)
                mloc = fmaxf(mloc, __shfl_xor_sync(0xffffffffu, mloc, off));
            float Mnew  = fmaxf(Mrow[i], mloc);
            float alpha = __expf(Mrow[i] - Mnew);
            Mrow[i] = Mnew;
            float p[8];
            float rs = 0.f;
#pragma unroll
            for (int j = 0; j < 8; ++j) {
                p[j] = __expf(w[j] - Mnew);
                rs += p[j];
            }
            float* prow = &Ps[(ty * 8 + i) * P_PITCH + tx * 8];
            *reinterpret_cast<float4*>(prow)     = make_float4(p[0], p[1], p[2], p[3]);
            *reinterpret_cast<float4*>(prow + 4) = make_float4(p[4], p[5], p[6], p[7]);
#pragma unroll
            for (int off = 8; off > 0; off >>= 1)
                rs += __shfl_xor_sync(0xffffffffu, rs, off);
            Lrow[i] = Lrow[i] * alpha + rs;
#pragma unroll
            for (int j = 0; j < 4; ++j) Oacc[i][j] *= alpha;
        }
        __syncthreads();

        /* ---- O += P @ V ---- */
#pragma unroll 4
        for (int c = 0; c < 128; ++c) {
            float4 v4 = *reinterpret_cast<const float4*>(&Vs[c * 64 + tx * 4]);
#pragma unroll
            for (int i = 0; i < 8; ++i) {
                float pv = Ps[(ty * 8 + i) * P_PITCH + c];
                Oacc[i][0] += pv * v4.x;
                Oacc[i][1] += pv * v4.y;
                Oacc[i][2] += pv * v4.z;
                Oacc[i][3] += pv * v4.w;
            }
        }
        __syncthreads();
    }

    /* ---- normalize + write back in [B,L,D] layout ---- */
    const int b = bh >> 4, h = bh & 15;
#pragma unroll
    for (int i = 0; i < 8; ++i) {
        int l = q0 + ty * 8 + i;
        float inv = __fdividef(1.f, Lrow[i]);
        size_t base = ((size_t)(b * L_SEQ + l)) * D_MODEL + h * D_HEAD + tx * 4;
#pragma unroll
        for (int j = 0; j < 4; ++j) Xout[base + j] = Oacc[i][j] * inv;
    }
}

/* ========================================================================= */
extern "C" void kernel_launch(void* const* d_in, const int* in_sizes, int n_in,
                              void* d_out, int out_size)
{
    (void)in_sizes; (void)n_in; (void)out_size;
    const float* query = (const float*)d_in[0];
    const float* key_  = (const float*)d_in[1];
    const float* value = (const float*)d_in[2];
    const float* Wq    = (const float*)d_in[3];
    const float* Wk    = (const float*)d_in[4];
    const float* Wv    = (const float*)d_in[5];
    const float* Wo    = (const float*)d_in[6];
    const float* bo    = (const float*)d_in[7];
    float* out = (float*)d_out;

    float *qp, *kp, *vp, *xp;
    cudaGetSymbolAddress((void**)&qp, g_q);
    cudaGetSymbolAddress((void**)&kp, g_k);
    cudaGetSymbolAddress((void**)&vp, g_v);
    cudaGetSymbolAddress((void**)&xp, g_x);

    dim3 ggrid(D_MODEL / 128, M_ROWS / 128);
    gemm_nt<<<ggrid, 256>>>(query, Wq, qp, nullptr, 1);
    gemm_nt<<<ggrid, 256>>>(key_,  Wk, kp, nullptr, 1);
    gemm_nt<<<ggrid, 256>>>(value, Wv, vp, nullptr, 1);

    size_t smem = (size_t)(64 * 128 * 2 + 128 * 64 + 128 * P_PITCH + 256) * sizeof(float);
    cudaFuncSetAttribute(attn_kernel, cudaFuncAttributeMaxDynamicSharedMemorySize, (int)smem);
    attn_kernel<<<dim3(L_SEQ / 128, BH), 256, smem>>>(qp, kp, vp, xp);

    gemm_nt<<<ggrid, 256>>>(xp, Wo, out, bo, 0);
}

// round 4
// speedup vs baseline: 1.4020x; 1.4020x over previous
#include <cuda_runtime.h>
#include <math.h>
#include <stdint.h>

#define L_SEQ   2048
#define D_MODEL 1024
#define N_HEADS 16
#define D_HEAD  64
#define BATCH   2
#define BH      (BATCH * N_HEADS)     /* 32  */
#define M_ROWS  (BATCH * L_SEQ)       /* 4096 */
#define SCALE_F 0.125f                /* Dh^-0.5 */
#define EPS_F   1e-9f
#define P_PITCH 132

/* ------------ scratch (static device globals: no allocation allowed) ------ */
__device__ __align__(16) float g_q[BH * L_SEQ * D_HEAD];
__device__ __align__(16) float g_k[BH * L_SEQ * D_HEAD];
__device__ __align__(16) float g_v[BH * L_SEQ * D_HEAD];
__device__ __align__(16) float g_x[(size_t)M_ROWS * D_MODEL];

/* =========================== mma.sync helpers ============================ */
__device__ __forceinline__ uint32_t f2tf32(float x)
{
    uint32_t r;
    asm("cvt.rna.tf32.f32 %0, %1;" : "=r"(r) : "f"(x));
    return r;
}

__device__ __forceinline__ uint4 cvt4(float4 v)
{
    return make_uint4(f2tf32(v.x), f2tf32(v.y), f2tf32(v.z), f2tf32(v.w));
}

__device__ __forceinline__ void mma_tf32(float* d, const uint32_t* a, const uint32_t* b)
{
    asm volatile(
        "mma.sync.aligned.m16n8k8.row.col.f32.tf32.tf32.f32 "
        "{%0,%1,%2,%3}, {%4,%5,%6,%7}, {%8,%9}, {%0,%1,%2,%3};"
        : "+f"(d[0]), "+f"(d[1]), "+f"(d[2]), "+f"(d[3])
        : "r"(a[0]), "r"(a[1]), "r"(a[2]), "r"(a[3]),
          "r"(b[0]), "r"(b[1]));
}

/* ===========================================================================
 * tf32 tensor-core GEMM: C = A @ W^T (+bias). A:[4096,1024], W:[1024,1024] rm.
 * CTA tile 128x128, BK=32, 256 thr (8 warps, 2m x 4n, warp tile 64x32).
 * SMEM in canonical mma-fragment layout [tile][reg][lane]:
 *   A elem (m,k): tile=(m>>4)*4+(k>>3), reg=((k>>2)&1)*2+((m>>3)&1),
 *                 lane=(m&7)*4+(k&3)          (tile block = 128 words)
 *   B elem (n,k): tile=(n>>3)*4+(k>>3), reg=(k>>2)&1,
 *                 lane=(n&7)*4+(k&3)          (tile block = 64 words)
 * -> stores are one st.shared.v4 per global float4 (conflict-free),
 *    fragment loads are conflict-free scalar LDS.
 * head_mode=1: scatter into [B,H,L,Dh]. head_mode=0: row-major + bias.
 * ========================================================================= */
#define GEMM_SMEM_BYTES 65536

__global__ __launch_bounds__(256)
void gemm_mma(const float* __restrict__ A, const float* __restrict__ W,
              float* __restrict__ C, const float* __restrict__ bias,
              int head_mode)
{
    extern __shared__ __align__(16) uint32_t smg[];
    uint32_t* As = smg;           /* [2][4096] */
    uint32_t* Bs = smg + 8192;    /* [2][4096] */

    const int tid = threadIdx.x;
    const int lane = tid & 31;
    const int wid = tid >> 5;
    const int warp_m = wid >> 2;   /* 0..1 */
    const int warp_n = wid & 3;    /* 0..3 */
    const int m0 = blockIdx.y * 128, n0 = blockIdx.x * 128;

    const int cc = tid & 7;        /* float4 index within the 32-wide k-tile */
    const int r0 = tid >> 3;       /* base row; rows r0 + 32*i               */

    int stA[4], stB[4];
#pragma unroll
    for (int i = 0; i < 4; ++i) {
        int rr = r0 + 32 * i;
        stA[i] = (((rr >> 4) * 4 + (cc >> 1)) * 128)
               + ((cc & 1) * 2 + ((rr >> 3) & 1)) * 32 + (rr & 7) * 4;
        stB[i] = (((rr >> 3) * 4 + (cc >> 1)) * 64)
               + (cc & 1) * 32 + (rr & 7) * 4;
    }

    float acc[4][4][4];
#pragma unroll
    for (int a = 0; a < 4; ++a)
#pragma unroll
        for (int b = 0; b < 4; ++b)
#pragma unroll
            for (int c = 0; c < 4; ++c) acc[a][b][c] = 0.f;

    const float* pA = A + (size_t)(m0 + r0) * D_MODEL + cc * 4;
    const float* pB = W + (size_t)(n0 + r0) * D_MODEL + cc * 4;

    float4 ga[4], gb[4];
#pragma unroll
    for (int i = 0; i < 4; ++i) {
        ga[i] = *reinterpret_cast<const float4*>(pA + (size_t)i * 32 * D_MODEL);
        gb[i] = *reinterpret_cast<const float4*>(pB + (size_t)i * 32 * D_MODEL);
    }
#pragma unroll
    for (int i = 0; i < 4; ++i) {
        *reinterpret_cast<uint4*>(&As[stA[i]]) = cvt4(ga[i]);
        *reinterpret_cast<uint4*>(&Bs[stB[i]]) = cvt4(gb[i]);
    }
    __syncthreads();

    for (int t = 0; t < 32; ++t) {
        const int buf = t & 1;
        if (t < 31) {
            const float* qA = pA + (t + 1) * 32;
            const float* qB = pB + (t + 1) * 32;
#pragma unroll
            for (int i = 0; i < 4; ++i) {
                ga[i] = *reinterpret_cast<const float4*>(qA + (size_t)i * 32 * D_MODEL);
                gb[i] = *reinterpret_cast<const float4*>(qB + (size_t)i * 32 * D_MODEL);
            }
        }
        const uint32_t* Ab = As + buf * 4096;
        const uint32_t* Bb = Bs + buf * 4096;
#pragma unroll
        for (int ks = 0; ks < 4; ++ks) {
            uint32_t af[4][4], bf[4][2];
#pragma unroll
            for (int mt = 0; mt < 4; ++mt) {
                int base = ((warp_m * 4 + mt) * 4 + ks) * 128 + lane;
                af[mt][0] = Ab[base];
                af[mt][1] = Ab[base + 32];
                af[mt][2] = Ab[base + 64];
                af[mt][3] = Ab[base + 96];
            }
#pragma unroll
            for (int nt = 0; nt < 4; ++nt) {
                int base = ((warp_n * 4 + nt) * 4 + ks) * 64 + lane;
                bf[nt][0] = Bb[base];
                bf[nt][1] = Bb[base + 32];
            }
#pragma unroll
            for (int mt = 0; mt < 4; ++mt)
#pragma unroll
                for (int nt = 0; nt < 4; ++nt)
                    mma_tf32(acc[mt][nt], af[mt], bf[nt]);
        }
        if (t < 31) {
            const int ob = buf ^ 1;
#pragma unroll
            for (int i = 0; i < 4; ++i) {
                *reinterpret_cast<uint4*>(&As[ob * 4096 + stA[i]]) = cvt4(ga[i]);
                *reinterpret_cast<uint4*>(&Bs[ob * 4096 + stB[i]]) = cvt4(gb[i]);
            }
        }
        __syncthreads();
    }

    /* ------------------------------ epilogue ----------------------------- */
    const int row_q = lane >> 2;
    const int col_q = (lane & 3) * 2;

    if (head_mode) {
#pragma unroll
        for (int mt = 0; mt < 4; ++mt)
#pragma unroll
            for (int nt = 0; nt < 4; ++nt) {
                int m = m0 + warp_m * 64 + mt * 16 + row_q;
                int n = n0 + warp_n * 32 + nt * 8 + col_q;
                int h = n >> 6, dh = n & 63;
                {
                    int bb = m >> 11, l = m & 2047;
                    *reinterpret_cast<float2*>(
                        &C[(((size_t)(bb * N_HEADS + h) * L_SEQ + l) << 6) + dh])
                        = make_float2(acc[mt][nt][0], acc[mt][nt][1]);
                }
                {
                    int m2 = m + 8;
                    int bb = m2 >> 11, l = m2 & 2047;
                    *reinterpret_cast<float2*>(
                        &C[(((size_t)(bb * N_HEADS + h) * L_SEQ + l) << 6) + dh])
                        = make_float2(acc[mt][nt][2], acc[mt][nt][3]);
                }
            }
    } else {
#pragma unroll
        for (int mt = 0; mt < 4; ++mt)
#pragma unroll
            for (int nt = 0; nt < 4; ++nt) {
                int m = m0 + warp_m * 64 + mt * 16 + row_q;
                int n = n0 + warp_n * 32 + nt * 8 + col_q;
                float2 bv = *reinterpret_cast<const float2*>(&bias[n]);
                *reinterpret_cast<float2*>(&C[(size_t)m * D_MODEL + n])
                    = make_float2(acc[mt][nt][0] + bv.x, acc[mt][nt][1] + bv.y);
                *reinterpret_cast<float2*>(&C[(size_t)(m + 8) * D_MODEL + n])
                    = make_float2(acc[mt][nt][2] + bv.x, acc[mt][nt][3] + bv.y);
            }
    }
}

/* ===========================================================================
 * Fused Euclidean flash-attention (unchanged; passes at ~1.25 ms).
 * ========================================================================= */
__device__ __forceinline__ int swz(int d, int r)
{
    return d * 128 + (r ^ (((d >> 2) & 7) << 2));
}

__global__ __launch_bounds__(256)
void attn_kernel(const float* __restrict__ Qh, const float* __restrict__ Kh,
                 const float* __restrict__ Vh, float* __restrict__ Xout)
{
    extern __shared__ float sm[];
    float* Qs  = sm;
    float* Ks  = Qs + 64 * 128;
    float* Vs  = Ks + 64 * 128;
    float* Ps  = Vs + 128 * 64;
    float* q2s = Ps + 128 * P_PITCH;
    float* k2s = q2s + 128;

    const int tid = threadIdx.x;
    const int tx = tid & 15, ty = tid >> 4;
    const int bh = blockIdx.y;
    const int q0 = blockIdx.x * 128;

    const float* Qb  = Qh + ((size_t)bh * L_SEQ + q0) * D_HEAD;
    const float* Kb0 = Kh + (size_t)bh * L_SEQ * D_HEAD;
    const float* Vb0 = Vh + (size_t)bh * L_SEQ * D_HEAD;

#pragma unroll
    for (int it = 0; it < 8; ++it) {
        int idx = tid + it * 256;
        int r = idx >> 4;
        int c = (idx & 15) * 4;
        float4 q4 = reinterpret_cast<const float4*>(Qb)[idx];
        Qs[swz(c + 0, r)] = q4.x;
        Qs[swz(c + 1, r)] = q4.y;
        Qs[swz(c + 2, r)] = q4.z;
        Qs[swz(c + 3, r)] = q4.w;
    }
    __syncthreads();
    if (tid < 128) {
        float s = 0.f;
#pragma unroll
        for (int d = 0; d < 64; ++d) { float x = Qs[swz(d, tid)]; s += x * x; }
        q2s[tid] = s;
    }

    float Mrow[8], Lrow[8], Oacc[8][4];
#pragma unroll
    for (int i = 0; i < 8; ++i) {
        Mrow[i] = -1e30f; Lrow[i] = 0.f;
#pragma unroll
        for (int j = 0; j < 4; ++j) Oacc[i][j] = 0.f;
    }
    __syncthreads();

    for (int kt = 0; kt < L_SEQ / 128; ++kt) {
        const float* Kb = Kb0 + (size_t)kt * 128 * D_HEAD;
        const float* Vb = Vb0 + (size_t)kt * 128 * D_HEAD;
#pragma unroll
        for (int it = 0; it < 8; ++it) {
            int idx = tid + it * 256;
            int r = idx >> 4;
            int c = (idx & 15) * 4;
            float4 k4 = reinterpret_cast<const float4*>(Kb)[idx];
            Ks[swz(c + 0, r)] = k4.x;
            Ks[swz(c + 1, r)] = k4.y;
            Ks[swz(c + 2, r)] = k4.z;
            Ks[swz(c + 3, r)] = k4.w;
            reinterpret_cast<float4*>(Vs)[idx] = reinterpret_cast<const float4*>(Vb)[idx];
        }
        __syncthreads();
        if (tid < 128) {
            float s = 0.f;
#pragma unroll
            for (int d = 0; d < 64; ++d) { float x = Ks[swz(d, tid)]; s += x * x; }
            k2s[tid] = s;
        }
        __syncthreads();

        float acc[8][8];
#pragma unroll
        for (int i = 0; i < 8; ++i)
#pragma unroll
            for (int j = 0; j < 8; ++j) acc[i][j] = 0.f;

#pragma unroll
        for (int d = 0; d < 64; ++d) {
            const int s  = (d >> 2) & 7;
            const int xh = (s >> 1) << 3;
            const int o0 = (s & 1) << 2;
            float aq[8], ak[8];
            {
                int b_ = d * 128 + ((ty << 3) ^ xh);
                *reinterpret_cast<float4*>(&aq[0]) = *reinterpret_cast<const float4*>(&Qs[b_ + o0]);
                *reinterpret_cast<float4*>(&aq[4]) = *reinterpret_cast<const float4*>(&Qs[b_ + (4 - o0)]);
            }
            {
                int b_ = d * 128 + ((tx << 3) ^ xh);
                *reinterpret_cast<float4*>(&ak[0]) = *reinterpret_cast<const float4*>(&Ks[b_ + o0]);
                *reinterpret_cast<float4*>(&ak[4]) = *reinterpret_cast<const float4*>(&Ks[b_ + (4 - o0)]);
            }
#pragma unroll
            for (int i = 0; i < 8; ++i)
#pragma unroll
                for (int j = 0; j < 8; ++j) acc[i][j] += aq[i] * ak[j];
        }

#pragma unroll
        for (int i = 0; i < 8; ++i) {
            float q2 = q2s[ty * 8 + i];
            float w[8];
            float mloc = -1e30f;
#pragma unroll
            for (int j = 0; j < 8; ++j) {
                float d2   = q2 + k2s[tx * 8 + j] - 2.f * acc[i][j];
                float dist = sqrtf(fmaxf(d2, 0.f));
                float wv   = __fdividef(1.f, dist * SCALE_F + EPS_F);
                w[j] = wv;
                mloc = fmaxf(mloc, wv);
            }
#pragma unroll
            for (int off = 8; off > 0; off >>= 1)
                mloc = fmaxf(mloc, __shfl_xor_sync(0xffffffffu, mloc, off));
            float Mnew  = fmaxf(Mrow[i], mloc);
            float alpha = __expf(Mrow[i] - Mnew);
            Mrow[i] = Mnew;
            float p[8];
            float rs = 0.f;
#pragma unroll
            for (int j = 0; j < 8; ++j) {
                p[j] = __expf(w[j] - Mnew);
                rs += p[j];
            }
            float* prow = &Ps[(ty * 8 + i) * P_PITCH + tx * 8];
            *reinterpret_cast<float4*>(prow)     = make_float4(p[0], p[1], p[2], p[3]);
            *reinterpret_cast<float4*>(prow + 4) = make_float4(p[4], p[5], p[6], p[7]);
#pragma unroll
            for (int off = 8; off > 0; off >>= 1)
                rs += __shfl_xor_sync(0xffffffffu, rs, off);
            Lrow[i] = Lrow[i] * alpha + rs;
#pragma unroll
            for (int j = 0; j < 4; ++j) Oacc[i][j] *= alpha;
        }
        __syncthreads();

#pragma unroll 4
        for (int c = 0; c < 128; ++c) {
            float4 v4 = *reinterpret_cast<const float4*>(&Vs[c * 64 + tx * 4]);
#pragma unroll
            for (int i = 0; i < 8; ++i) {
                float pv = Ps[(ty * 8 + i) * P_PITCH + c];
                Oacc[i][0] += pv * v4.x;
                Oacc[i][1] += pv * v4.y;
                Oacc[i][2] += pv * v4.z;
                Oacc[i][3] += pv * v4.w;
            }
        }
        __syncthreads();
    }

    const int b = bh >> 4, h = bh & 15;
#pragma unroll
    for (int i = 0; i < 8; ++i) {
        int l = q0 + ty * 8 + i;
        float inv = __fdividef(1.f, Lrow[i]);
        size_t base = ((size_t)(b * L_SEQ + l)) * D_MODEL + h * D_HEAD + tx * 4;
#pragma unroll
        for (int j = 0; j < 4; ++j) Xout[base + j] = Oacc[i][j] * inv;
    }
}

/* ========================================================================= */
extern "C" void kernel_launch(void* const* d_in, const int* in_sizes, int n_in,
                              void* d_out, int out_size)
{
    (void)in_sizes; (void)n_in; (void)out_size;
    const float* query = (const float*)d_in[0];
    const float* key_  = (const float*)d_in[1];
    const float* value = (const float*)d_in[2];
    const float* Wq    = (const float*)d_in[3];
    const float* Wk    = (const float*)d_in[4];
    const float* Wv    = (const float*)d_in[5];
    const float* Wo    = (const float*)d_in[6];
    const float* bo    = (const float*)d_in[7];
    float* out = (float*)d_out;

    float *qp, *kp, *vp, *xp;
    cudaGetSymbolAddress((void**)&qp, g_q);
    cudaGetSymbolAddress((void**)&kp, g_k);
    cudaGetSymbolAddress((void**)&vp, g_v);
    cudaGetSymbolAddress((void**)&xp, g_x);

    cudaFuncSetAttribute(gemm_mma, cudaFuncAttributeMaxDynamicSharedMemorySize,
                         GEMM_SMEM_BYTES);

    dim3 ggrid(D_MODEL / 128, M_ROWS / 128);
    gemm_mma<<<ggrid, 256, GEMM_SMEM_BYTES>>>(query, Wq, qp, nullptr, 1);
    gemm_mma<<<ggrid, 256, GEMM_SMEM_BYTES>>>(key_,  Wk, kp, nullptr, 1);
    gemm_mma<<<ggrid, 256, GEMM_SMEM_BYTES>>>(value, Wv, vp, nullptr, 1);

    size_t smem = (size_t)(64 * 128 * 2 + 128 * 64 + 128 * P_PITCH + 256) * sizeof(float);
    cudaFuncSetAttribute(attn_kernel, cudaFuncAttributeMaxDynamicSharedMemorySize, (int)smem);
    attn_kernel<<<dim3(L_SEQ / 128, BH), 256, smem>>>(qp, kp, vp, xp);

    gemm_mma<<<ggrid, 256, GEMM_SMEM_BYTES>>>(xp, Wo, out, bo, 0);
}

// round 5
// speedup vs baseline: 2.5234x; 1.7999x over previous
#include <cuda_runtime.h>
#include <math.h>
#include <stdint.h>

#define L_SEQ   2048
#define D_MODEL 1024
#define N_HEADS 16
#define D_HEAD  64
#define BATCH   2
#define BH      (BATCH * N_HEADS)     /* 32  */
#define M_ROWS  (BATCH * L_SEQ)       /* 4096 */

/* ------------ scratch (static device globals: no allocation allowed) ------ */
__device__ __align__(16) float g_q[BH * L_SEQ * D_HEAD];
__device__ __align__(16) float g_k[BH * L_SEQ * D_HEAD];
__device__ __align__(16) float g_v[BH * L_SEQ * D_HEAD];
__device__ __align__(16) float g_x[(size_t)M_ROWS * D_MODEL];

/* =========================== mma.sync helpers ============================ */
__device__ __forceinline__ uint32_t f2tf32(float x)
{
    uint32_t r;
    asm("cvt.rna.tf32.f32 %0, %1;" : "=r"(r) : "f"(x));
    return r;
}

__device__ __forceinline__ uint4 cvt4(float4 v)
{
    return make_uint4(f2tf32(v.x), f2tf32(v.y), f2tf32(v.z), f2tf32(v.w));
}

__device__ __forceinline__ void mma_tf32(float* d, const uint32_t* a, const uint32_t* b)
{
    asm volatile(
        "mma.sync.aligned.m16n8k8.row.col.f32.tf32.tf32.f32 "
        "{%0,%1,%2,%3}, {%4,%5,%6,%7}, {%8,%9}, {%0,%1,%2,%3};"
        : "+f"(d[0]), "+f"(d[1]), "+f"(d[2]), "+f"(d[3])
        : "r"(a[0]), "r"(a[1]), "r"(a[2]), "r"(a[3]),
          "r"(b[0]), "r"(b[1]));
}

/* fragment-layout smem offsets (words), with bank swizzle.
 * A-frag element (m,k), KT = number of 8-wide k-tiles:
 *   block=(m>>4)*KT+(k>>3) (128 words), reg=((k>>2)&1)*2+((m>>3)&1),
 *   inner=((m&7)<<2|(k&3)) ^ ((k>>3)&7)<<2
 * B-frag element (n,k):
 *   block=(n>>3)*KT+(k>>3) (64 words), reg=(k>>2)&1,
 *   inner=((n&7)<<2|(k&3)) ^ (((n>>3)&7)^((k>>3)&7))<<2           */
__device__ __forceinline__ int offA(int m, int k, int KT)
{
    return ((m >> 4) * KT + (k >> 3)) * 128
         + (((k >> 2) & 1) * 2 + ((m >> 3) & 1)) * 32
         + ((((m & 7) << 2) | (k & 3)) ^ ((((k >> 3) & 7)) << 2));
}
__device__ __forceinline__ int offB(int n, int k, int KT)
{
    return ((n >> 3) * KT + (k >> 3)) * 64
         + (((k >> 2) & 1)) * 32
         + ((((n & 7) << 2) | (k & 3)) ^ ((((n >> 3) & 7) ^ ((k >> 3) & 7)) << 2));
}

/* ===========================================================================
 * tf32 tensor-core GEMM (unchanged from R4 — passes at ~112 us each).
 * ========================================================================= */
#define GEMM_SMEM_BYTES 65536

__global__ __launch_bounds__(256)
void gemm_mma(const float* __restrict__ A, const float* __restrict__ W,
              float* __restrict__ C, const float* __restrict__ bias,
              int head_mode)
{
    extern __shared__ __align__(16) uint32_t smg[];
    uint32_t* As = smg;           /* [2][4096] */
    uint32_t* Bs = smg + 8192;    /* [2][4096] */

    const int tid = threadIdx.x;
    const int lane = tid & 31;
    const int wid = tid >> 5;
    const int warp_m = wid >> 2;
    const int warp_n = wid & 3;
    const int m0 = blockIdx.y * 128, n0 = blockIdx.x * 128;

    const int cc = tid & 7;
    const int r0 = tid >> 3;

    int stA[4], stB[4];
#pragma unroll
    for (int i = 0; i < 4; ++i) {
        int rr = r0 + 32 * i;
        stA[i] = (((rr >> 4) * 4 + (cc >> 1)) * 128)
               + ((cc & 1) * 2 + ((rr >> 3) & 1)) * 32 + (rr & 7) * 4;
        stB[i] = (((rr >> 3) * 4 + (cc >> 1)) * 64)
               + (cc & 1) * 32 + (rr & 7) * 4;
    }

    float acc[4][4][4];
#pragma unroll
    for (int a = 0; a < 4; ++a)
#pragma unroll
        for (int b = 0; b < 4; ++b)
#pragma unroll
            for (int c = 0; c < 4; ++c) acc[a][b][c] = 0.f;

    const float* pA = A + (size_t)(m0 + r0) * D_MODEL + cc * 4;
    const float* pB = W + (size_t)(n0 + r0) * D_MODEL + cc * 4;

    float4 ga[4], gb[4];
#pragma unroll
    for (int i = 0; i < 4; ++i) {
        ga[i] = *reinterpret_cast<const float4*>(pA + (size_t)i * 32 * D_MODEL);
        gb[i] = *reinterpret_cast<const float4*>(pB + (size_t)i * 32 * D_MODEL);
    }
#pragma unroll
    for (int i = 0; i < 4; ++i) {
        *reinterpret_cast<uint4*>(&As[stA[i]]) = cvt4(ga[i]);
        *reinterpret_cast<uint4*>(&Bs[stB[i]]) = cvt4(gb[i]);
    }
    __syncthreads();

    for (int t = 0; t < 32; ++t) {
        const int buf = t & 1;
        if (t < 31) {
            const float* qA = pA + (t + 1) * 32;
            const float* qB = pB + (t + 1) * 32;
#pragma unroll
            for (int i = 0; i < 4; ++i) {
                ga[i] = *reinterpret_cast<const float4*>(qA + (size_t)i * 32 * D_MODEL);
                gb[i] = *reinterpret_cast<const float4*>(qB + (size_t)i * 32 * D_MODEL);
            }
        }
        const uint32_t* Ab = As + buf * 4096;
        const uint32_t* Bb = Bs + buf * 4096;
#pragma unroll
        for (int ks = 0; ks < 4; ++ks) {
            uint32_t af[4][4], bf[4][2];
#pragma unroll
            for (int mt = 0; mt < 4; ++mt) {
                int base = ((warp_m * 4 + mt) * 4 + ks) * 128 + lane;
                af[mt][0] = Ab[base];
                af[mt][1] = Ab[base + 32];
                af[mt][2] = Ab[base + 64];
                af[mt][3] = Ab[base + 96];
            }
#pragma unroll
            for (int nt = 0; nt < 4; ++nt) {
                int base = ((warp_n * 4 + nt) * 4 + ks) * 64 + lane;
                bf[nt][0] = Bb[base];
                bf[nt][1] = Bb[base + 32];
            }
#pragma unroll
            for (int mt = 0; mt < 4; ++mt)
#pragma unroll
                for (int nt = 0; nt < 4; ++nt)
                    mma_tf32(acc[mt][nt], af[mt], bf[nt]);
        }
        if (t < 31) {
            const int ob = buf ^ 1;
#pragma unroll
            for (int i = 0; i < 4; ++i) {
                *reinterpret_cast<uint4*>(&As[ob * 4096 + stA[i]]) = cvt4(ga[i]);
                *reinterpret_cast<uint4*>(&Bs[ob * 4096 + stB[i]]) = cvt4(gb[i]);
            }
        }
        __syncthreads();
    }

    const int row_q = lane >> 2;
    const int col_q = (lane & 3) * 2;

    if (head_mode) {
#pragma unroll
        for (int mt = 0; mt < 4; ++mt)
#pragma unroll
            for (int nt = 0; nt < 4; ++nt) {
                int m = m0 + warp_m * 64 + mt * 16 + row_q;
                int n = n0 + warp_n * 32 + nt * 8 + col_q;
                int h = n >> 6, dh = n & 63;
                {
                    int bb = m >> 11, l = m & 2047;
                    *reinterpret_cast<float2*>(
                        &C[(((size_t)(bb * N_HEADS + h) * L_SEQ + l) << 6) + dh])
                        = make_float2(acc[mt][nt][0], acc[mt][nt][1]);
                }
                {
                    int m2 = m + 8;
                    int bb = m2 >> 11, l = m2 & 2047;
                    *reinterpret_cast<float2*>(
                        &C[(((size_t)(bb * N_HEADS + h) * L_SEQ + l) << 6) + dh])
                        = make_float2(acc[mt][nt][2], acc[mt][nt][3]);
                }
            }
    } else {
#pragma unroll
        for (int mt = 0; mt < 4; ++mt)
#pragma unroll
            for (int nt = 0; nt < 4; ++nt) {
                int m = m0 + warp_m * 64 + mt * 16 + row_q;
                int n = n0 + warp_n * 32 + nt * 8 + col_q;
                float2 bv = *reinterpret_cast<const float2*>(&bias[n]);
                *reinterpret_cast<float2*>(&C[(size_t)m * D_MODEL + n])
                    = make_float2(acc[mt][nt][0] + bv.x, acc[mt][nt][1] + bv.y);
                *reinterpret_cast<float2*>(&C[(size_t)(m + 8) * D_MODEL + n])
                    = make_float2(acc[mt][nt][2] + bv.x, acc[mt][nt][3] + bv.y);
            }
    }
}

/* ===========================================================================
 * Euclidean flash-attention on tensor cores (tf32 mma for S=QK^T and P@V).
 * Grid (16 q-tiles, 32 heads), 256 threads.
 * w = 1/(dist*scale+eps) == 8*rsqrt(d2) (eps=1e-9 negligible, clamp w<=70);
 * no online max needed (w is O(1)); row sums accumulate across tiles.
 * SMEM: Qf(A-frag,32KB) Kf(B,32KB) Vf(B,32KB) Pf(A,64KB) q2/k2/rs.
 * ========================================================================= */
#define ATT_SMEM_WORDS (8192 * 3 + 16384 + 128 + 128 + 4 * 128)
#define ATT_SMEM_BYTES (ATT_SMEM_WORDS * 4)

__global__ __launch_bounds__(256, 1)
void attn_mma(const float* __restrict__ Qh, const float* __restrict__ Kh,
              const float* __restrict__ Vh, float* __restrict__ Xout)
{
    extern __shared__ __align__(16) uint32_t smw[];
    uint32_t* Qf = smw;                 /* A-frag, KT=8  : 8192 words  */
    uint32_t* Kf = Qf + 8192;           /* B-frag, KT=8  : 8192 words  */
    uint32_t* Vf = Kf + 8192;           /* B-frag, KT=16 : 8192 words  */
    uint32_t* Pf = Vf + 8192;           /* A-frag, KT=16 : 16384 words */
    float* q2 = (float*)(Pf + 16384);   /* [128]       */
    float* k2 = q2 + 128;               /* [128]       */
    float* rs = k2 + 128;               /* [4][128]    */

    const int tid  = threadIdx.x;
    const int lane = tid & 31;
    const int wid  = tid >> 5;
    const int warp_m  = wid >> 2;       /* S phase: 2m x 4n  */
    const int warp_n  = wid & 3;
    const int warp_m2 = wid >> 1;       /* PV phase: 4m x 2n */
    const int warp_n2 = wid & 1;
    const int bh = blockIdx.y;
    const int q0 = blockIdx.x * 128;

    /* ---- load Q tile into A-frag layout + q2 (from tf32-rounded values) -- */
    const float4* Qg4 = reinterpret_cast<const float4*>(
        Qh + ((size_t)bh * L_SEQ + q0) * D_HEAD);
#pragma unroll
    for (int it = 0; it < 8; ++it) {
        int idx = it * 256 + tid;
        int m = idx >> 4, c4 = idx & 15, k0 = c4 * 4;
        uint4 u = cvt4(Qg4[idx]);
        *reinterpret_cast<uint4*>(&Qf[offA(m, k0, 8)]) = u;
        float a = __uint_as_float(u.x), b = __uint_as_float(u.y);
        float c = __uint_as_float(u.z), d = __uint_as_float(u.w);
        float part = a * a + b * b + c * c + d * d;
        part += __shfl_xor_sync(0xffffffffu, part, 1);
        part += __shfl_xor_sync(0xffffffffu, part, 2);
        part += __shfl_xor_sync(0xffffffffu, part, 4);
        part += __shfl_xor_sync(0xffffffffu, part, 8);
        if (c4 == 0) q2[m] = part;
    }

    float oacc[2][4][4];
#pragma unroll
    for (int a = 0; a < 2; ++a)
#pragma unroll
        for (int b = 0; b < 4; ++b)
#pragma unroll
            for (int c = 0; c < 4; ++c) oacc[a][b][c] = 0.f;
    float rsum[4][2];
#pragma unroll
    for (int a = 0; a < 4; ++a) { rsum[a][0] = 0.f; rsum[a][1] = 0.f; }

    const float4* Kg4 = reinterpret_cast<const float4*>(
        Kh + (size_t)bh * L_SEQ * D_HEAD);
    const float4* Vg4 = reinterpret_cast<const float4*>(
        Vh + (size_t)bh * L_SEQ * D_HEAD);

    for (int kt = 0; kt < 16; ++kt) {
        /* ---- load K tile (B-frag) + k2, V tile (transposed B-frag) ------- */
#pragma unroll
        for (int it = 0; it < 8; ++it) {
            int idx = it * 256 + tid;
            int n = idx >> 4, c4 = idx & 15, k0 = c4 * 4;
            uint4 u = cvt4(Kg4[kt * 2048 + idx]);
            *reinterpret_cast<uint4*>(&Kf[offB(n, k0, 8)]) = u;
            float a = __uint_as_float(u.x), b = __uint_as_float(u.y);
            float c = __uint_as_float(u.z), d = __uint_as_float(u.w);
            float part = a * a + b * b + c * c + d * d;
            part += __shfl_xor_sync(0xffffffffu, part, 1);
            part += __shfl_xor_sync(0xffffffffu, part, 2);
            part += __shfl_xor_sync(0xffffffffu, part, 4);
            part += __shfl_xor_sync(0xffffffffu, part, 8);
            if (c4 == 0) k2[n] = part;

            /* V: element (k=row kr, n=4*c4v+j) -> B-frag (n, k) */
            int kr = idx >> 4, n0v = (idx & 15) * 4;
            float4 vv = Vg4[kt * 2048 + idx];
            Vf[offB(n0v + 0, kr, 16)] = f2tf32(vv.x);
            Vf[offB(n0v + 1, kr, 16)] = f2tf32(vv.y);
            Vf[offB(n0v + 2, kr, 16)] = f2tf32(vv.z);
            Vf[offB(n0v + 3, kr, 16)] = f2tf32(vv.w);
        }
        __syncthreads();

        /* ---- S = Q.K^T via mma (warp tile 64x32) -------------------------- */
        float sacc[4][4][4];
#pragma unroll
        for (int a = 0; a < 4; ++a)
#pragma unroll
            for (int b = 0; b < 4; ++b)
#pragma unroll
                for (int c = 0; c < 4; ++c) sacc[a][b][c] = 0.f;

#pragma unroll
        for (int ks = 0; ks < 8; ++ks) {
            uint32_t af[4][4], bf[4][2];
#pragma unroll
            for (int mt = 0; mt < 4; ++mt) {
                int base = ((warp_m * 4 + mt) * 8 + ks) * 128
                         + (lane ^ ((ks & 7) << 2));
                af[mt][0] = Qf[base];
                af[mt][1] = Qf[base + 32];
                af[mt][2] = Qf[base + 64];
                af[mt][3] = Qf[base + 96];
            }
#pragma unroll
            for (int nt = 0; nt < 4; ++nt) {
                int Nt = warp_n * 4 + nt;
                int base = (Nt * 8 + ks) * 64
                         + (lane ^ ((((Nt & 7) ^ (ks & 7))) << 2));
                bf[nt][0] = Kf[base];
                bf[nt][1] = Kf[base + 32];
            }
#pragma unroll
            for (int mt = 0; mt < 4; ++mt)
#pragma unroll
                for (int nt = 0; nt < 4; ++nt)
                    mma_tf32(sacc[mt][nt], af[mt], bf[nt]);
        }

        /* ---- euclid weights, exp, row-sum accumulate, stage P ------------- */
#pragma unroll
        for (int mt = 0; mt < 4; ++mt) {
            int m1 = warp_m * 64 + mt * 16 + (lane >> 2);
            float q2a = q2[m1], q2b = q2[m1 + 8];
#pragma unroll
            for (int nt = 0; nt < 4; ++nt) {
                int c0 = warp_n * 32 + nt * 8 + (lane & 3) * 2;
                float k2a = k2[c0], k2b = k2[c0 + 1];
                float d0 = fmaxf(fmaf(sacc[mt][nt][0], -2.f, q2a + k2a), 1e-24f);
                float d1 = fmaxf(fmaf(sacc[mt][nt][1], -2.f, q2a + k2b), 1e-24f);
                float d2 = fmaxf(fmaf(sacc[mt][nt][2], -2.f, q2b + k2a), 1e-24f);
                float d3 = fmaxf(fmaf(sacc[mt][nt][3], -2.f, q2b + k2b), 1e-24f);
                float p0 = __expf(fminf(rsqrtf(d0) * 8.f, 70.f));
                float p1 = __expf(fminf(rsqrtf(d1) * 8.f, 70.f));
                float p2 = __expf(fminf(rsqrtf(d2) * 8.f, 70.f));
                float p3 = __expf(fminf(rsqrtf(d3) * 8.f, 70.f));
                rsum[mt][0] += p0 + p1;
                rsum[mt][1] += p2 + p3;
                *reinterpret_cast<uint2*>(&Pf[offA(m1, c0, 16)])
                    = make_uint2(f2tf32(p0), f2tf32(p1));
                *reinterpret_cast<uint2*>(&Pf[offA(m1 + 8, c0, 16)])
                    = make_uint2(f2tf32(p2), f2tf32(p3));
            }
        }
        __syncthreads();

        /* ---- O += P @ V via mma (warp tile 32x32, K=128) ------------------ */
#pragma unroll 4
        for (int ks2 = 0; ks2 < 16; ++ks2) {
            uint32_t pf[2][4], vf[4][2];
#pragma unroll
            for (int mt2 = 0; mt2 < 2; ++mt2) {
                int base = ((warp_m2 * 2 + mt2) * 16 + ks2) * 128
                         + (lane ^ ((ks2 & 7) << 2));
                pf[mt2][0] = Pf[base];
                pf[mt2][1] = Pf[base + 32];
                pf[mt2][2] = Pf[base + 64];
                pf[mt2][3] = Pf[base + 96];
            }
#pragma unroll
            for (int nt2 = 0; nt2 < 4; ++nt2) {
                int Nt2 = warp_n2 * 4 + nt2;
                int base = (Nt2 * 16 + ks2) * 64
                         + (lane ^ ((((Nt2 & 7) ^ (ks2 & 7))) << 2));
                vf[nt2][0] = Vf[base];
                vf[nt2][1] = Vf[base + 32];
            }
#pragma unroll
            for (int mt2 = 0; mt2 < 2; ++mt2)
#pragma unroll
                for (int nt2 = 0; nt2 < 4; ++nt2)
                    mma_tf32(oacc[mt2][nt2], pf[mt2], vf[nt2]);
        }
        __syncthreads();
    }

    /* ---- cross-warp row-sum reduce ---------------------------------------- */
#pragma unroll
    for (int mt = 0; mt < 4; ++mt)
#pragma unroll
        for (int rh = 0; rh < 2; ++rh) {
            float r = rsum[mt][rh];
            r += __shfl_xor_sync(0xffffffffu, r, 1);
            r += __shfl_xor_sync(0xffffffffu, r, 2);
            if ((lane & 3) == 0)
                rs[warp_n * 128 + warp_m * 64 + mt * 16 + rh * 8 + (lane >> 2)] = r;
        }
    __syncthreads();

    /* ---- normalize + writeback [B,L,D] ------------------------------------ */
    const int b = bh >> 4, h = bh & 15;
#pragma unroll
    for (int mt2 = 0; mt2 < 2; ++mt2) {
        int m = warp_m2 * 32 + mt2 * 16 + (lane >> 2);
        float s1 = rs[m] + rs[128 + m] + rs[256 + m] + rs[384 + m];
        float s2 = rs[m + 8] + rs[128 + m + 8] + rs[256 + m + 8] + rs[384 + m + 8];
        float inv1 = __fdividef(1.f, s1);
        float inv2 = __fdividef(1.f, s2);
#pragma unroll
        for (int nt2 = 0; nt2 < 4; ++nt2) {
            int c = warp_n2 * 32 + nt2 * 8 + (lane & 3) * 2;
            size_t b1 = ((size_t)(b * L_SEQ + q0 + m)) * D_MODEL + h * 64 + c;
            size_t b2 = ((size_t)(b * L_SEQ + q0 + m + 8)) * D_MODEL + h * 64 + c;
            *reinterpret_cast<float2*>(&Xout[b1])
                = make_float2(oacc[mt2][nt2][0] * inv1, oacc[mt2][nt2][1] * inv1);
            *reinterpret_cast<float2*>(&Xout[b2])
                = make_float2(oacc[mt2][nt2][2] * inv2, oacc[mt2][nt2][3] * inv2);
        }
    }
}

/* ========================================================================= */
extern "C" void kernel_launch(void* const* d_in, const int* in_sizes, int n_in,
                              void* d_out, int out_size)
{
    (void)in_sizes; (void)n_in; (void)out_size;
    const float* query = (const float*)d_in[0];
    const float* key_  = (const float*)d_in[1];
    const float* value = (const float*)d_in[2];
    const float* Wq    = (const float*)d_in[3];
    const float* Wk    = (const float*)d_in[4];
    const float* Wv    = (const float*)d_in[5];
    const float* Wo    = (const float*)d_in[6];
    const float* bo    = (const float*)d_in[7];
    float* out = (float*)d_out;

    float *qp, *kp, *vp, *xp;
    cudaGetSymbolAddress((void**)&qp, g_q);
    cudaGetSymbolAddress((void**)&kp, g_k);
    cudaGetSymbolAddress((void**)&vp, g_v);
    cudaGetSymbolAddress((void**)&xp, g_x);

    cudaFuncSetAttribute(gemm_mma, cudaFuncAttributeMaxDynamicSharedMemorySize,
                         GEMM_SMEM_BYTES);
    cudaFuncSetAttribute(attn_mma, cudaFuncAttributeMaxDynamicSharedMemorySize,
                         ATT_SMEM_BYTES);

    dim3 ggrid(D_MODEL / 128, M_ROWS / 128);
    gemm_mma<<<ggrid, 256, GEMM_SMEM_BYTES>>>(query, Wq, qp, nullptr, 1);
    gemm_mma<<<ggrid, 256, GEMM_SMEM_BYTES>>>(key_,  Wk, kp, nullptr, 1);
    gemm_mma<<<ggrid, 256, GEMM_SMEM_BYTES>>>(value, Wv, vp, nullptr, 1);

    attn_mma<<<dim3(16, BH), 256, ATT_SMEM_BYTES>>>(qp, kp, vp, xp);

    gemm_mma<<<ggrid, 256, GEMM_SMEM_BYTES>>>(xp, Wo, out, bo, 0);
}